// round 16
// baseline (speedup 1.0000x reference)
#include <cuda_runtime.h>
#include <cuda_bf16.h>

// FINAL KERNEL (converged) — harness replay floor ~6.5 +/- 0.2 us over 5 runs.
//
// Session findings:
//  * Algorithmic: the reference's 8192x8192 pairwise-distance matrix is never
//    needed — the output is ~16.4K directly gathered distances computed from X.
//  * Overhead-bound: <1% DRAM, ~3% issue; ncu kernel durations of 4.5-7.2 us
//    across all variants map to the same ~6.5 us end-to-end band.
//  * Block-shape sweep (128x49/129, 256x65/97, 512x33): 256x65 best mean.
//  * R7 regression: >8 outstanding loads per thread serializes under the
//    16-reg MLP budget (+2.7 us) — one thread per output item is optimal.
//  * X-row vector loads rejected: 12B rows are 8B-aligned only for even rows.
//  * L1D is flushed per launch on sm_103a — every replay pays the L2 hops;
//    no kernel-side change can shorten the critical path further.

// Problem constants (match reference_code)
#define NPTS 8192
#define F0   8191      // N - 1 finite dim-0 pairs
#define E0   1
#define F1   4096
#define E1   8

// Output layout (flat fp32):
//   [0,     16382)  finite_dgm0   : rows (0, death)   -> float2 per row
//   [16382, 16383)  essential_dgm0: single 0
//   [16383, 24575)  finite_dgm1   : 2*F1 gathered dists
//   [24575, 24583)  essential_dgm1: E1 gathered dists
#define OFF_E0  (2 * F0)            // 16382
#define OFF_F1  (OFF_E0 + E0)       // 16383
#define OFF_E1  (OFF_F1 + 2 * F1)   // 24575

#define ITEM_F1   (F0 + 1)              // 8192
#define ITEM_E1   (ITEM_F1 + 2 * F1)    // 16384
#define N_ITEMS   (ITEM_E1 + E1)        // 16392

__device__ __forceinline__ float pair_dist(const float* __restrict__ X, int a, int b) {
    float ax = __ldg(X + 3 * a + 0);
    float ay = __ldg(X + 3 * a + 1);
    float az = __ldg(X + 3 * a + 2);
    float bx = __ldg(X + 3 * b + 0);
    float by = __ldg(X + 3 * b + 1);
    float bz = __ldg(X + 3 * b + 2);
    float dx = ax - bx, dy = ay - by, dz = az - bz;
    return sqrtf(fmaf(dx, dx, fmaf(dy, dy, dz * dz)));
}

__global__ __launch_bounds__(256, 4)
void rips_kernel(const float* __restrict__ X,
                 const int* __restrict__ idx0_finite,    // [F0,3]
                 const int* __restrict__ idx1_finite,    // [F1,4] == flat pairs [2*F1,2]
                 const int* __restrict__ idx1_essential, // [E1,2]
                 float* __restrict__ out) {
    int tid = blockIdx.x * blockDim.x + threadIdx.x;
    if (tid >= N_ITEMS) return;

    if (tid < F0) {
        // One dgm0 row: independent index loads issue back-to-back, then six
        // X loads, then one 8B store of (0, death).
        int a = __ldg(idx0_finite + 3 * tid + 1);
        int b = __ldg(idx0_finite + 3 * tid + 2);
        float d = pair_dist(X, a, b);
        *reinterpret_cast<float2*>(out + 2 * tid) = make_float2(0.0f, d);
    } else if (tid == F0) {
        out[OFF_E0] = 0.0f;  // essential_dgm0
    } else if (tid < ITEM_E1) {
        int j = tid - ITEM_F1;  // flat pair index [0, 2*F1)
        int2 p = __ldg(reinterpret_cast<const int2*>(idx1_finite) + j);  // 8B-aligned
        out[OFF_F1 + j] = pair_dist(X, p.x, p.y);
    } else {
        int k = tid - ITEM_E1;
        int2 p = __ldg(reinterpret_cast<const int2*>(idx1_essential) + k);
        out[OFF_E1 + k] = pair_dist(X, p.x, p.y);
    }
}

extern "C" void kernel_launch(void* const* d_in, const int* in_sizes, int n_in,
                              void* d_out, int out_size) {
    const float* X              = (const float*)d_in[0];
    const int*   idx0_finite    = (const int*)d_in[1];
    // d_in[2] = idx0_essential (unused; corresponding outputs are zeros)
    const int*   idx1_finite    = (const int*)d_in[3];
    const int*   idx1_essential = (const int*)d_in[4];
    float* out = (float*)d_out;

    const int threads = 256;
    const int blocks = (N_ITEMS + threads - 1) / threads;  // 65
    rips_kernel<<<blocks, threads>>>(X, idx0_finite, idx1_finite, idx1_essential, out);
}

// round 17
// speedup vs baseline: 1.0597x; 1.0597x over previous
#include <cuda_runtime.h>
#include <cuda_bf16.h>

// FINAL KERNEL (converged) — harness replay floor ~6.6 +/- 0.2 us over 6 runs.
//
// Session findings:
//  * Algorithmic: the reference's 8192x8192 pairwise-distance matrix is never
//    needed — the output is ~16.4K directly gathered distances computed from X.
//  * Overhead-bound: <1% DRAM, ~3% issue; ncu kernel durations of 4.5-7.2 us
//    across all variants map to the same ~6.6 us end-to-end band.
//  * Block-shape sweep (128x49/129, 256x65/97, 512x33): 256x65 best mean.
//  * R7 regression: >8 outstanding loads per thread serializes under the
//    16-reg MLP budget (+2.7 us) — one thread per output item is optimal.
//  * X-row vector loads rejected: 12B rows are 8B-aligned only for even rows.
//  * L1D is flushed per launch on sm_103a — every replay pays the L2 hops;
//    no kernel-side change can shorten the critical path further.

// Problem constants (match reference_code)
#define NPTS 8192
#define F0   8191      // N - 1 finite dim-0 pairs
#define E0   1
#define F1   4096
#define E1   8

// Output layout (flat fp32):
//   [0,     16382)  finite_dgm0   : rows (0, death)   -> float2 per row
//   [16382, 16383)  essential_dgm0: single 0
//   [16383, 24575)  finite_dgm1   : 2*F1 gathered dists
//   [24575, 24583)  essential_dgm1: E1 gathered dists
#define OFF_E0  (2 * F0)            // 16382
#define OFF_F1  (OFF_E0 + E0)       // 16383
#define OFF_E1  (OFF_F1 + 2 * F1)   // 24575

#define ITEM_F1   (F0 + 1)              // 8192
#define ITEM_E1   (ITEM_F1 + 2 * F1)    // 16384
#define N_ITEMS   (ITEM_E1 + E1)        // 16392

__device__ __forceinline__ float pair_dist(const float* __restrict__ X, int a, int b) {
    float ax = __ldg(X + 3 * a + 0);
    float ay = __ldg(X + 3 * a + 1);
    float az = __ldg(X + 3 * a + 2);
    float bx = __ldg(X + 3 * b + 0);
    float by = __ldg(X + 3 * b + 1);
    float bz = __ldg(X + 3 * b + 2);
    float dx = ax - bx, dy = ay - by, dz = az - bz;
    return sqrtf(fmaf(dx, dx, fmaf(dy, dy, dz * dz)));
}

__global__ __launch_bounds__(256, 4)
void rips_kernel(const float* __restrict__ X,
                 const int* __restrict__ idx0_finite,    // [F0,3]
                 const int* __restrict__ idx1_finite,    // [F1,4] == flat pairs [2*F1,2]
                 const int* __restrict__ idx1_essential, // [E1,2]
                 float* __restrict__ out) {
    int tid = blockIdx.x * blockDim.x + threadIdx.x;
    if (tid >= N_ITEMS) return;

    if (tid < F0) {
        // One dgm0 row: independent index loads issue back-to-back, then six
        // X loads, then one 8B store of (0, death).
        int a = __ldg(idx0_finite + 3 * tid + 1);
        int b = __ldg(idx0_finite + 3 * tid + 2);
        float d = pair_dist(X, a, b);
        *reinterpret_cast<float2*>(out + 2 * tid) = make_float2(0.0f, d);
    } else if (tid == F0) {
        out[OFF_E0] = 0.0f;  // essential_dgm0
    } else if (tid < ITEM_E1) {
        int j = tid - ITEM_F1;  // flat pair index [0, 2*F1)
        int2 p = __ldg(reinterpret_cast<const int2*>(idx1_finite) + j);  // 8B-aligned
        out[OFF_F1 + j] = pair_dist(X, p.x, p.y);
    } else {
        int k = tid - ITEM_E1;
        int2 p = __ldg(reinterpret_cast<const int2*>(idx1_essential) + k);
        out[OFF_E1 + k] = pair_dist(X, p.x, p.y);
    }
}

extern "C" void kernel_launch(void* const* d_in, const int* in_sizes, int n_in,
                              void* d_out, int out_size) {
    const float* X              = (const float*)d_in[0];
    const int*   idx0_finite    = (const int*)d_in[1];
    // d_in[2] = idx0_essential (unused; corresponding outputs are zeros)
    const int*   idx1_finite    = (const int*)d_in[3];
    const int*   idx1_essential = (const int*)d_in[4];
    float* out = (float*)d_out;

    const int threads = 256;
    const int blocks = (N_ITEMS + threads - 1) / threads;  // 65
    rips_kernel<<<blocks, threads>>>(X, idx0_finite, idx1_finite, idx1_essential, out);
}